// round 3
// baseline (speedup 1.0000x reference)
#include <cuda_runtime.h>
#include <math.h>

#define BB 16
#define NN 2048
#define MM 32
#define PP 48
#define TT 5
#define CC (PP*TT)   // 240

#define APB 8        // atoms per block (kernel 1)
#define TH1 (APB*64) // 512 threads = 16 warps; phase A uses warps 0..APB-1

// Per-n BatchNorm statistics, accumulated by rsf_kernel via atomics.
__device__ float g_sum [NN];
__device__ float g_sum2[NN];

// ---------------------------------------------------------------------------
// Kernel 0: zero the stats accumulators (must precede rsf each replay).
// ---------------------------------------------------------------------------
__global__ void zero_stats_kernel()
{
    const int i = blockIdx.x * blockDim.x + threadIdx.x;
    if (i < NN) { g_sum[i] = 0.0f; g_sum2[i] = 0.0f; }
}

// ---------------------------------------------------------------------------
// Kernel 1: radial symmetry functions, bucketed by atom type + fused BN stats.
// Phase A: warp w (< APB) handles atom (blockIdx*APB + w); lane = neighbor m.
//          Computes R, maps Z -> type bin, compacts valid R's into per-type
//          buckets in shared memory via warp ballot (invalid Z dropped).
// Phase B: 64-thread group g handles atom g; thread j < 48 is radial index p.
//          Accumulates exp(-re (R-rs)^2)*cutoff per type bucket, writes
//          layer[b,n, t*48+p] to d_out, and reduces sum/sumsq for BN stats.
// ---------------------------------------------------------------------------
__global__ __launch_bounds__(TH1)
void rsf_kernel(const float* __restrict__ X,
                const float* __restrict__ rc,
                const float* __restrict__ rs,
                const float* __restrict__ re,
                const int*   __restrict__ Nbrs,
                const int*   __restrict__ NbrsZ,
                float*       __restrict__ out)
{
    __shared__ float sR[APB][MM];
    __shared__ int   sOff[APB][TT + 1];

    const int tid  = threadIdx.x;
    const int warp = tid >> 5;
    const int lane = tid & 31;
    const int baseAtom = blockIdx.x * APB;      // atom = b*N + n

    // ---------------- Phase A: one warp per atom (warps 0..APB-1) ----------
    if (warp < APB) {
        const int atom = baseAtom + warp;
        const int b    = atom >> 11;            // atom / N
        const float* xp = X + atom * 3;
        const float x0 = xp[0], x1 = xp[1], x2 = xp[2];

        const int nb = Nbrs [atom * MM + lane];
        const int z  = NbrsZ[atom * MM + lane];
        const float* np_ = X + ((b << 11) + nb) * 3;
        const float dx = np_[0] - x0;
        const float dy = np_[1] - x1;
        const float dz = np_[2] - x2;
        const float R  = sqrtf(dx*dx + dy*dy + dz*dz);

        int t = -1;
        if      (z == 1)  t = 0;
        else if (z == 6)  t = 1;
        else if (z == 7)  t = 2;
        else if (z == 8)  t = 3;
        else if (z == 16) t = 4;

        int base = 0;
        const unsigned lt = (1u << lane) - 1u;
        #pragma unroll
        for (int tt = 0; tt < TT; tt++) {
            unsigned mask = __ballot_sync(0xffffffffu, t == tt);
            if (t == tt) {
                sR[warp][base + __popc(mask & lt)] = R;
            }
            if (lane == 0) sOff[warp][tt] = base;
            base += __popc(mask);
        }
        if (lane == 0) sOff[warp][TT] = base;
    }
    __syncthreads();

    // ---------------- Phase B: 64-thread group per atom ----------------
    const int g = tid >> 6;        // atom within block (0..APB-1)
    const int j = tid & 63;        // p index (j < 48 active)
    const int atom = baseAtom + g;

    float s = 0.0f, s2 = 0.0f;     // BN partial sums (0 for inactive j)
    if (j < PP) {
        const float myrc  = rc[j];
        const float myrs  = rs[j];
        const float nre   = -re[j];
        const float pi_rc = 3.14159265358979f / myrc;
        float* op = out + (size_t)atom * CC;

        #pragma unroll
        for (int tt = 0; tt < TT; tt++) {
            const int mb = sOff[g][tt];
            const int me = sOff[g][tt + 1];
            float acc = 0.0f;
            for (int m = mb; m < me; m++) {
                const float R  = sR[g][m];
                const float dr = R - myrs;
                const float ex = __expf(nre * dr * dr);
                const float fc = 0.5f * __cosf(R * pi_rc) + 0.5f;
                const float v  = ex * fc;
                acc += (R <= myrc) ? v : 0.0f;
            }
            op[tt * PP + j] = acc;
            s  += acc;
            s2 += acc * acc;
        }
    }

    // Warp-level reduction of BN partials; one atomic per warp per value.
    #pragma unroll
    for (int o = 16; o > 0; o >>= 1) {
        s  += __shfl_down_sync(0xffffffffu, s,  o);
        s2 += __shfl_down_sync(0xffffffffu, s2, o);
    }
    if (lane == 0) {
        const int n = atom & (NN - 1);
        atomicAdd(&g_sum[n],  s);
        atomicAdd(&g_sum2[n], s2);
    }
}

// ---------------------------------------------------------------------------
// Kernel 2: normalize. One block per (b,n) row; 240 active threads do a
// single load + FMA + store. Stats broadcast from L2.
// ---------------------------------------------------------------------------
__global__ __launch_bounds__(256)
void norm_kernel(float* __restrict__ out)
{
    const int atom = blockIdx.x;            // b*N + n
    const int n    = atom & (NN - 1);
    const int tid  = threadIdx.x;

    const float invn = 1.0f / (float)(BB * CC);
    const float mean = g_sum[n] * invn;
    float var = g_sum2[n] * invn - mean * mean;
    var = fmaxf(var, 0.0f);
    const float inv = rsqrtf(var + 1e-5f);

    if (tid < CC) {
        const size_t idx = (size_t)atom * CC + tid;
        out[idx] = (out[idx] - mean) * inv;
    }
}

// ---------------------------------------------------------------------------
extern "C" void kernel_launch(void* const* d_in, const int* in_sizes, int n_in,
                              void* d_out, int out_size)
{
    const float* X     = (const float*)d_in[0];
    const float* rc    = (const float*)d_in[1];
    const float* rs    = (const float*)d_in[2];
    const float* re    = (const float*)d_in[3];
    const int*   Nbrs  = (const int*)  d_in[4];
    const int*   NbrsZ = (const int*)  d_in[5];
    float* out = (float*)d_out;

    const int nAtoms = BB * NN;                 // 32768
    zero_stats_kernel<<<(NN + 255) / 256, 256>>>();
    rsf_kernel<<<nAtoms / APB, TH1>>>(X, rc, rs, re, Nbrs, NbrsZ, out);
    norm_kernel<<<nAtoms, 256>>>(out);
}

// round 4
// speedup vs baseline: 1.7594x; 1.7594x over previous
#include <cuda_runtime.h>
#include <math.h>

#define BB 16
#define NN 2048
#define MM 32
#define PP 48
#define TT 5
#define CC (PP*TT)   // 240

#define APB 8        // atoms per block (kernel 1)
#define TH1 (APB*64) // 512 threads = 16 warps; phase A uses warps 0..APB-1

// Per-atom BN partials: g_part[atom] = {sum, sumsq} over the 240 channels.
// Unconditionally overwritten every launch -> no zeroing, fully deterministic.
__device__ float2 g_part[BB * NN];

// ---------------------------------------------------------------------------
// Kernel 1: radial symmetry functions, bucketed by atom type + BN partials.
// Phase A: warp w (< APB) handles atom (blockIdx*APB + w); lane = neighbor m.
//          Computes R, maps Z -> type bin, compacts valid R's into per-type
//          buckets in shared memory via warp ballot (invalid Z dropped).
// Phase B: 64-thread group g handles atom g; thread j < 48 is radial index p.
//          Accumulates exp(-re (R-rs)^2)*cutoff per type bucket, writes
//          layer[b,n, t*48+p] to d_out; per-atom sum/sumsq -> g_part.
// ---------------------------------------------------------------------------
__global__ __launch_bounds__(TH1)
void rsf_kernel(const float* __restrict__ X,
                const float* __restrict__ rc,
                const float* __restrict__ rs,
                const float* __restrict__ re,
                const int*   __restrict__ Nbrs,
                const int*   __restrict__ NbrsZ,
                float*       __restrict__ out)
{
    __shared__ float sR[APB][MM];
    __shared__ int   sOff[APB][TT + 1];
    __shared__ float sS[TH1 / 32], sS2[TH1 / 32];   // per-warp partials

    const int tid  = threadIdx.x;
    const int warp = tid >> 5;
    const int lane = tid & 31;
    const int baseAtom = blockIdx.x * APB;      // atom = b*N + n

    // ---------------- Phase A: one warp per atom (warps 0..APB-1) ----------
    if (warp < APB) {
        const int atom = baseAtom + warp;
        const int b    = atom >> 11;            // atom / N
        const float* xp = X + atom * 3;
        const float x0 = xp[0], x1 = xp[1], x2 = xp[2];

        const int nb = Nbrs [atom * MM + lane];
        const int z  = NbrsZ[atom * MM + lane];
        const float* np_ = X + ((b << 11) + nb) * 3;
        const float dx = np_[0] - x0;
        const float dy = np_[1] - x1;
        const float dz = np_[2] - x2;
        const float R  = sqrtf(dx*dx + dy*dy + dz*dz);

        int t = -1;
        if      (z == 1)  t = 0;
        else if (z == 6)  t = 1;
        else if (z == 7)  t = 2;
        else if (z == 8)  t = 3;
        else if (z == 16) t = 4;

        int base = 0;
        const unsigned lt = (1u << lane) - 1u;
        #pragma unroll
        for (int tt = 0; tt < TT; tt++) {
            unsigned mask = __ballot_sync(0xffffffffu, t == tt);
            if (t == tt) {
                sR[warp][base + __popc(mask & lt)] = R;
            }
            if (lane == 0) sOff[warp][tt] = base;
            base += __popc(mask);
        }
        if (lane == 0) sOff[warp][TT] = base;
    }
    __syncthreads();

    // ---------------- Phase B: 64-thread group per atom ----------------
    const int g = tid >> 6;        // atom within block (0..APB-1)
    const int j = tid & 63;        // p index (j < 48 active)
    const int atom = baseAtom + g;

    float s = 0.0f, s2 = 0.0f;     // BN partial sums (0 for inactive j)
    if (j < PP) {
        const float myrc  = rc[j];
        const float myrs  = rs[j];
        const float nre   = -re[j];
        const float pi_rc = 3.14159265358979f / myrc;
        float* op = out + (size_t)atom * CC;

        #pragma unroll
        for (int tt = 0; tt < TT; tt++) {
            const int mb = sOff[g][tt];
            const int me = sOff[g][tt + 1];
            float acc = 0.0f;
            for (int m = mb; m < me; m++) {
                const float R  = sR[g][m];
                const float dr = R - myrs;
                const float ex = __expf(nre * dr * dr);
                const float fc = 0.5f * __cosf(R * pi_rc) + 0.5f;
                const float v  = ex * fc;
                acc += (R <= myrc) ? v : 0.0f;
            }
            op[tt * PP + j] = acc;
            s  += acc;
            s2 += acc * acc;
        }
    }

    // Warp-level reduction, then combine the two warps of each atom group.
    #pragma unroll
    for (int o = 16; o > 0; o >>= 1) {
        s  += __shfl_down_sync(0xffffffffu, s,  o);
        s2 += __shfl_down_sync(0xffffffffu, s2, o);
    }
    if (lane == 0) { sS[warp] = s; sS2[warp] = s2; }
    __syncthreads();
    if (tid < APB) {
        float2 p;
        p.x = sS [2*tid] + sS [2*tid + 1];
        p.y = sS2[2*tid] + sS2[2*tid + 1];
        g_part[baseAtom + tid] = p;
    }
}

// ---------------------------------------------------------------------------
// Kernel 2: BatchNorm normalize. One block per n (2048 blocks, 256 threads).
// Warp 0 reduces the 16 per-atom partials -> mean/inv; then a b-unrolled
// stream pass (16 loads batched, then 16 stores) normalizes in place.
// ---------------------------------------------------------------------------
__global__ __launch_bounds__(256)
void norm_kernel(float* __restrict__ out)
{
    const int n   = blockIdx.x;
    const int tid = threadIdx.x;

    __shared__ float sMean, sInv;

    if (tid < 32) {
        float s = 0.0f, s2 = 0.0f;
        if (tid < BB) {
            const float2 p = g_part[tid * NN + n];
            s = p.x; s2 = p.y;
        }
        #pragma unroll
        for (int o = 8; o > 0; o >>= 1) {
            s  += __shfl_down_sync(0xffffffffu, s,  o);
            s2 += __shfl_down_sync(0xffffffffu, s2, o);
        }
        if (tid == 0) {
            const float invn = 1.0f / (float)(BB * CC);
            const float mean = s * invn;
            float var = s2 * invn - mean * mean;
            var = fmaxf(var, 0.0f);
            sMean = mean;
            sInv  = rsqrtf(var + 1e-5f);
        }
    }
    __syncthreads();

    const float mean = sMean;
    const float inv  = sInv;

    if (tid < CC) {
        float vals[BB];
        #pragma unroll
        for (int b = 0; b < BB; b++) {
            vals[b] = out[((size_t)(b * NN + n)) * CC + tid];
        }
        #pragma unroll
        for (int b = 0; b < BB; b++) {
            out[((size_t)(b * NN + n)) * CC + tid] = (vals[b] - mean) * inv;
        }
    }
}

// ---------------------------------------------------------------------------
extern "C" void kernel_launch(void* const* d_in, const int* in_sizes, int n_in,
                              void* d_out, int out_size)
{
    const float* X     = (const float*)d_in[0];
    const float* rc    = (const float*)d_in[1];
    const float* rs    = (const float*)d_in[2];
    const float* re    = (const float*)d_in[3];
    const int*   Nbrs  = (const int*)  d_in[4];
    const int*   NbrsZ = (const int*)  d_in[5];
    float* out = (float*)d_out;

    const int nAtoms = BB * NN;                 // 32768
    rsf_kernel<<<nAtoms / APB, TH1>>>(X, rc, rs, re, Nbrs, NbrsZ, out);
    norm_kernel<<<NN, 256>>>(out);
}

// round 5
// speedup vs baseline: 1.8753x; 1.0659x over previous
#include <cuda_runtime.h>
#include <math.h>

#define BB 16
#define NN 2048
#define MM 32
#define PP 48
#define TT 5
#define CC (PP*TT)   // 240

#define APB 4        // atoms per block (kernel 1) -- validated R1 geometry
#define TH1 256      // 8 warps; phase A uses warps 0..APB-1

// Per-atom BN partials: g_part[atom] = {sum, sumsq} over the 240 channels.
// Unconditionally overwritten every launch -> no zeroing, fully deterministic.
__device__ float2 g_part[BB * NN];

// ---------------------------------------------------------------------------
// Kernel 1: radial symmetry functions, bucketed by atom type + BN partials.
// Phase A: warp w (< APB) handles atom (blockIdx*APB + w); lane = neighbor m.
//          Computes R, maps Z -> type bin, compacts valid R's into per-type
//          buckets in shared memory via warp ballot (invalid Z dropped).
// Phase B: 64-thread group g handles atom g; thread j < 48 is radial index p.
//          acc_t = sum over bucket t of exp2(nre2 (R-rs)^2) * cutoff(R),
//          written to layer[b,n, t*48+j]; per-atom sum/sumsq -> g_part.
// ---------------------------------------------------------------------------
__global__ __launch_bounds__(TH1)
void rsf_kernel(const float* __restrict__ X,
                const float* __restrict__ rc,
                const float* __restrict__ rs,
                const float* __restrict__ re,
                const int*   __restrict__ Nbrs,
                const int*   __restrict__ NbrsZ,
                float*       __restrict__ out)
{
    __shared__ float sR[APB][MM];
    __shared__ int   sOff[APB][TT + 1];
    __shared__ float sS[TH1 / 32], sS2[TH1 / 32];   // per-warp partials

    const int tid  = threadIdx.x;
    const int warp = tid >> 5;
    const int lane = tid & 31;
    const int baseAtom = blockIdx.x * APB;      // atom = b*N + n

    // ---------------- Phase A: one warp per atom (warps 0..APB-1) ----------
    if (warp < APB) {
        const int atom = baseAtom + warp;
        const int b    = atom >> 11;            // atom / N
        const float* xp = X + atom * 3;
        const float x0 = xp[0], x1 = xp[1], x2 = xp[2];

        const int nb = Nbrs [atom * MM + lane];
        const int z  = NbrsZ[atom * MM + lane];
        const float* np_ = X + ((b << 11) + nb) * 3;
        const float dx = np_[0] - x0;
        const float dy = np_[1] - x1;
        const float dz = np_[2] - x2;
        const float R  = sqrtf(dx*dx + dy*dy + dz*dz);

        int t = -1;
        if      (z == 1)  t = 0;
        else if (z == 6)  t = 1;
        else if (z == 7)  t = 2;
        else if (z == 8)  t = 3;
        else if (z == 16) t = 4;

        int base = 0;
        const unsigned lt = (1u << lane) - 1u;
        #pragma unroll
        for (int tt = 0; tt < TT; tt++) {
            unsigned mask = __ballot_sync(0xffffffffu, t == tt);
            if (t == tt) {
                sR[warp][base + __popc(mask & lt)] = R;
            }
            if (lane == 0) sOff[warp][tt] = base;
            base += __popc(mask);
        }
        if (lane == 0) sOff[warp][TT] = base;
    }
    __syncthreads();

    // ---------------- Phase B: 64-thread group per atom ----------------
    const int g = tid >> 6;        // atom within block (0..APB-1)
    const int j = tid & 63;        // p index (j < 48 active)
    const int atom = baseAtom + g;

    float s = 0.0f, s2 = 0.0f;     // BN partial sums (0 for inactive j)
    if (j < PP) {
        const float myrc  = rc[j];
        const float myrs  = rs[j];
        const float nre2  = -re[j] * 1.44269504088896f;  // fold log2(e)
        const float pi_rc = 3.14159265358979f / myrc;
        float* op = out + (size_t)atom * CC;
        const float* rrow = sR[g];

        #pragma unroll
        for (int tt = 0; tt < TT; tt++) {
            const int mb = sOff[g][tt];
            const int me = sOff[g][tt + 1];
            float acc = 0.0f;
            int m = mb;
            for (; m + 1 < me; m += 2) {
                const float R0 = rrow[m];
                const float R1 = rrow[m + 1];
                const float d0 = R0 - myrs;
                const float d1 = R1 - myrs;
                const float e0 = exp2f(nre2 * d0 * d0);
                const float e1 = exp2f(nre2 * d1 * d1);
                const float c0 = __cosf(R0 * pi_rc);
                const float c1 = __cosf(R1 * pi_rc);
                const float f0 = (R0 <= myrc) ? fmaf(c0, 0.5f, 0.5f) : 0.0f;
                const float f1 = (R1 <= myrc) ? fmaf(c1, 0.5f, 0.5f) : 0.0f;
                acc = fmaf(e0, f0, acc);
                acc = fmaf(e1, f1, acc);
            }
            if (m < me) {
                const float R0 = rrow[m];
                const float d0 = R0 - myrs;
                const float e0 = exp2f(nre2 * d0 * d0);
                const float c0 = __cosf(R0 * pi_rc);
                const float f0 = (R0 <= myrc) ? fmaf(c0, 0.5f, 0.5f) : 0.0f;
                acc = fmaf(e0, f0, acc);
            }
            op[tt * PP + j] = acc;
            s  += acc;
            s2 = fmaf(acc, acc, s2);
        }
    }

    // Warp-level reduction, then combine the two warps of each atom group.
    #pragma unroll
    for (int o = 16; o > 0; o >>= 1) {
        s  += __shfl_down_sync(0xffffffffu, s,  o);
        s2 += __shfl_down_sync(0xffffffffu, s2, o);
    }
    if (lane == 0) { sS[warp] = s; sS2[warp] = s2; }
    __syncthreads();
    if (tid < APB) {
        float2 p;
        p.x = sS [2*tid] + sS [2*tid + 1];
        p.y = sS2[2*tid] + sS2[2*tid + 1];
        g_part[baseAtom + tid] = p;
    }
}

// ---------------------------------------------------------------------------
// Kernel 2: BatchNorm normalize. One block per n (2048 blocks, 256 threads).
// Warp 0 reduces the 16 per-atom partials -> mean/inv; then a b-unrolled
// stream pass (16 loads batched, then 16 stores) normalizes in place.
// ---------------------------------------------------------------------------
__global__ __launch_bounds__(256)
void norm_kernel(float* __restrict__ out)
{
    const int n   = blockIdx.x;
    const int tid = threadIdx.x;

    __shared__ float sMean, sInv;

    if (tid < 32) {
        float s = 0.0f, s2 = 0.0f;
        if (tid < BB) {
            const float2 p = g_part[tid * NN + n];
            s = p.x; s2 = p.y;
        }
        #pragma unroll
        for (int o = 8; o > 0; o >>= 1) {
            s  += __shfl_down_sync(0xffffffffu, s,  o);
            s2 += __shfl_down_sync(0xffffffffu, s2, o);
        }
        if (tid == 0) {
            const float invn = 1.0f / (float)(BB * CC);
            const float mean = s * invn;
            float var = s2 * invn - mean * mean;
            var = fmaxf(var, 0.0f);
            sMean = mean;
            sInv  = rsqrtf(var + 1e-5f);
        }
    }
    __syncthreads();

    const float mean = sMean;
    const float inv  = sInv;

    if (tid < CC) {
        float vals[BB];
        #pragma unroll
        for (int b = 0; b < BB; b++) {
            vals[b] = out[((size_t)(b * NN + n)) * CC + tid];
        }
        #pragma unroll
        for (int b = 0; b < BB; b++) {
            out[((size_t)(b * NN + n)) * CC + tid] = (vals[b] - mean) * inv;
        }
    }
}

// ---------------------------------------------------------------------------
extern "C" void kernel_launch(void* const* d_in, const int* in_sizes, int n_in,
                              void* d_out, int out_size)
{
    const float* X     = (const float*)d_in[0];
    const float* rc    = (const float*)d_in[1];
    const float* rs    = (const float*)d_in[2];
    const float* re    = (const float*)d_in[3];
    const int*   Nbrs  = (const int*)  d_in[4];
    const int*   NbrsZ = (const int*)  d_in[5];
    float* out = (float*)d_out;

    const int nAtoms = BB * NN;                 // 32768
    rsf_kernel<<<nAtoms / APB, TH1>>>(X, rc, rs, re, Nbrs, NbrsZ, out);
    norm_kernel<<<NN, 256>>>(out);
}

// round 6
// speedup vs baseline: 2.0366x; 1.0860x over previous
#include <cuda_runtime.h>
#include <math.h>

#define BB 16
#define NN 2048
#define MM 32
#define PP 48
#define TT 5
#define CC (PP*TT)   // 240

#define APB 8            // atoms per block
#define TH1 (APB*PP)     // 384 threads = 12 warps; phase A uses warps 0..7

// Per-atom BN partials: g_part[atom] = {sum, sumsq} over 240 channels.
// Unconditionally overwritten every launch -> deterministic, no zeroing.
__device__ float2 g_part[BB * NN];

__device__ __forceinline__ float ex2_fast(float x) {
    float r; asm("ex2.approx.f32 %0, %1;" : "=f"(r) : "f"(x)); return r;
}
__device__ __forceinline__ float sqrt_fast(float x) {
    float r; asm("sqrt.approx.f32 %0, %1;" : "=f"(r) : "f"(x)); return r;
}

// ---------------------------------------------------------------------------
// Kernel 1: radial symmetry functions + BN partials.
// Phase A (warps 0..7): warp w = atom, lane = neighbor. Compute R, map Z to
//   type bin; single-ballot compaction of VALID neighbors into sRT[w][] as
//   float2(R, type_bits). Invalid Z (12/17 of entries) dropped entirely.
// Phase B (all 384 threads): thread q -> atom g = q/48, radial idx j = q%48.
//   One uniform loop over total valid neighbors; 5 predicated adds route each
//   contribution to its type accumulator. Writes layer[atom, t*48+j].
// Phase C (warps 0..7): per-atom reduce of per-thread (s,s2) -> g_part.
// ---------------------------------------------------------------------------
__global__ __launch_bounds__(TH1)
void rsf_kernel(const float* __restrict__ X,
                const float* __restrict__ rc,
                const float* __restrict__ rs,
                const float* __restrict__ re,
                const int*   __restrict__ Nbrs,
                const int*   __restrict__ NbrsZ,
                float*       __restrict__ out)
{
    __shared__ float2 sRT[APB][MM];
    __shared__ int    sCnt[APB];
    __shared__ float2 sPart[TH1];

    const int tid  = threadIdx.x;
    const int warp = tid >> 5;
    const int lane = tid & 31;
    const int baseAtom = blockIdx.x * APB;      // atom = b*N + n

    // ---------------- Phase A ----------------
    if (warp < APB) {
        const int atom = baseAtom + warp;
        const int b    = atom >> 11;
        const float* xp = X + atom * 3;
        const float x0 = xp[0], x1 = xp[1], x2 = xp[2];

        const int nb = Nbrs [atom * MM + lane];
        const int z  = NbrsZ[atom * MM + lane];
        const float* np_ = X + ((b << 11) + nb) * 3;
        const float dx = np_[0] - x0;
        const float dy = np_[1] - x1;
        const float dz = np_[2] - x2;
        const float R  = sqrt_fast(dx*dx + dy*dy + dz*dz);

        int t = -1;
        if      (z == 1)  t = 0;
        else if (z == 6)  t = 1;
        else if (z == 7)  t = 2;
        else if (z == 8)  t = 3;
        else if (z == 16) t = 4;

        const unsigned mask = __ballot_sync(0xffffffffu, t >= 0);
        if (t >= 0) {
            const int pos = __popc(mask & ((1u << lane) - 1u));
            sRT[warp][pos] = make_float2(R, __int_as_float(t));
        }
        if (lane == 0) sCnt[warp] = __popc(mask);
    }
    __syncthreads();

    // ---------------- Phase B ----------------
    const int g = tid / PP;        // atom within block
    const int j = tid % PP;        // radial index p
    const int atom = baseAtom + g;

    const float myrc  = rc[j];
    const float myrs  = rs[j];
    const float nre2  = -re[j] * 1.44269504088896f;  // fold log2(e)
    const float pi_rc = 3.14159265358979f / myrc;
    const float2* rt  = sRT[g];
    const int total   = sCnt[g];

    float acc[TT];
    #pragma unroll
    for (int tt = 0; tt < TT; tt++) acc[tt] = 0.0f;

    int m = 0;
    for (; m + 2 <= total; m += 2) {
        const float2 a0 = rt[m];
        const float2 a1 = rt[m + 1];
        const float R0 = a0.x, R1 = a1.x;
        const int   t0 = __float_as_int(a0.y);
        const int   t1 = __float_as_int(a1.y);
        const float d0 = R0 - myrs;
        const float d1 = R1 - myrs;
        const float e0 = ex2_fast(nre2 * d0 * d0);
        const float e1 = ex2_fast(nre2 * d1 * d1);
        const float c0 = __cosf(R0 * pi_rc);
        const float c1 = __cosf(R1 * pi_rc);
        float f0 = fmaf(c0, 0.5f, 0.5f);
        float f1 = fmaf(c1, 0.5f, 0.5f);
        f0 = (R0 <= myrc) ? f0 : 0.0f;
        f1 = (R1 <= myrc) ? f1 : 0.0f;
        const float v0 = e0 * f0;
        const float v1 = e1 * f1;
        #pragma unroll
        for (int tt = 0; tt < TT; tt++) {
            if (t0 == tt) acc[tt] += v0;
            if (t1 == tt) acc[tt] += v1;
        }
    }
    if (m < total) {
        const float2 a0 = rt[m];
        const float R0 = a0.x;
        const int   t0 = __float_as_int(a0.y);
        const float d0 = R0 - myrs;
        const float e0 = ex2_fast(nre2 * d0 * d0);
        const float c0 = __cosf(R0 * pi_rc);
        float f0 = fmaf(c0, 0.5f, 0.5f);
        f0 = (R0 <= myrc) ? f0 : 0.0f;
        const float v0 = e0 * f0;
        #pragma unroll
        for (int tt = 0; tt < TT; tt++) {
            if (t0 == tt) acc[tt] += v0;
        }
    }

    float s = 0.0f, s2 = 0.0f;
    {
        float* op = out + (size_t)atom * CC;
        #pragma unroll
        for (int tt = 0; tt < TT; tt++) {
            const float a = acc[tt];
            op[tt * PP + j] = a;
            s  += a;
            s2 = fmaf(a, a, s2);
        }
    }
    sPart[tid] = make_float2(s, s2);
    __syncthreads();

    // ---------------- Phase C: per-atom reduce of (s,s2) ----------------
    if (warp < APB) {
        const float2 p0 = sPart[warp * PP + lane];
        float s  = p0.x;
        float s2 = p0.y;
        if (lane < PP - 32) {
            const float2 p1 = sPart[warp * PP + 32 + lane];
            s  += p1.x;
            s2 += p1.y;
        }
        #pragma unroll
        for (int o = 16; o > 0; o >>= 1) {
            s  += __shfl_down_sync(0xffffffffu, s,  o);
            s2 += __shfl_down_sync(0xffffffffu, s2, o);
        }
        if (lane == 0) g_part[baseAtom + warp] = make_float2(s, s2);
    }
}

// ---------------------------------------------------------------------------
// Kernel 2: BatchNorm normalize. Grid = NN*4; block (n, chunk) handles 4 of
// the 16 b-rows for column n as float4 (one vec load + store per thread).
// ---------------------------------------------------------------------------
__global__ __launch_bounds__(256)
void norm_kernel(float4* __restrict__ out4)
{
    const int n     = blockIdx.x >> 2;
    const int chunk = blockIdx.x & 3;
    const int tid   = threadIdx.x;

    __shared__ float sMean, sInv;

    if (tid < 32) {
        float s = 0.0f, s2 = 0.0f;
        if (tid < BB) {
            const float2 p = g_part[tid * NN + n];
            s = p.x; s2 = p.y;
        }
        #pragma unroll
        for (int o = 8; o > 0; o >>= 1) {
            s  += __shfl_down_sync(0xffffffffu, s,  o);
            s2 += __shfl_down_sync(0xffffffffu, s2, o);
        }
        if (tid == 0) {
            const float invn = 1.0f / (float)(BB * CC);
            const float mean = s * invn;
            float var = s2 * invn - mean * mean;
            var = fmaxf(var, 0.0f);
            sMean = mean;
            sInv  = rsqrtf(var + 1e-5f);
        }
    }
    __syncthreads();

    if (tid < 240) {
        const float mean = sMean;
        const float inv  = sInv;
        const int r  = tid / 60;              // row within chunk (0..3)
        const int c4 = tid % 60;              // float4 index within row
        const int b  = chunk * 4 + r;
        const size_t idx = (size_t)(b * NN + n) * (CC / 4) + c4;
        float4 v = out4[idx];
        v.x = (v.x - mean) * inv;
        v.y = (v.y - mean) * inv;
        v.z = (v.z - mean) * inv;
        v.w = (v.w - mean) * inv;
        out4[idx] = v;
    }
}

// ---------------------------------------------------------------------------
extern "C" void kernel_launch(void* const* d_in, const int* in_sizes, int n_in,
                              void* d_out, int out_size)
{
    const float* X     = (const float*)d_in[0];
    const float* rc    = (const float*)d_in[1];
    const float* rs    = (const float*)d_in[2];
    const float* re    = (const float*)d_in[3];
    const int*   Nbrs  = (const int*)  d_in[4];
    const int*   NbrsZ = (const int*)  d_in[5];

    const int nAtoms = BB * NN;                 // 32768
    rsf_kernel<<<nAtoms / APB, TH1>>>(X, rc, rs, re, Nbrs, NbrsZ, (float*)d_out);
    norm_kernel<<<NN * 4, 256>>>((float4*)d_out);
}

// round 7
// speedup vs baseline: 2.1310x; 1.0463x over previous
#include <cuda_runtime.h>
#include <math.h>

#define BB 16
#define NN 2048
#define MM 32
#define PP 48
#define TT 5
#define CC (PP*TT)   // 240

#define APB 8            // atoms per block
#define TH1 (APB*PP)     // 384 threads = 12 warps; phase A uses warps 0..7

// Per-atom BN partials: g_part[atom] = {sum, sumsq} over 240 channels.
// Unconditionally overwritten every launch -> deterministic, no zeroing.
__device__ float2 g_part[BB * NN];

__device__ __forceinline__ float ex2_fast(float x) {
    float r; asm("ex2.approx.f32 %0, %1;" : "=f"(r) : "f"(x)); return r;
}
__device__ __forceinline__ float sqrt_fast(float x) {
    float r; asm("sqrt.approx.f32 %0, %1;" : "=f"(r) : "f"(x)); return r;
}

// ---------------------------------------------------------------------------
// Kernel 1: radial symmetry functions + BN partials.
// Phase A (warps 0..7): warp w = atom, lane = neighbor. Compute R, map Z to
//   type bin; single-ballot compaction of VALID neighbors into sRT[w][] as
//   float2(R, type_bits). Invalid Z (12/17 of entries) dropped entirely.
// Phase B (all 384 threads): thread q -> atom g = q/48, radial idx j = q%48.
//   One uniform loop over valid neighbors; 5 predicated adds route each
//   contribution to its type accumulator. Writes layer[atom, t*48+j].
// Phase C (warps 0..7): per-atom reduce of per-thread (s,s2) -> g_part.
// ---------------------------------------------------------------------------
__global__ __launch_bounds__(TH1, 4)
void rsf_kernel(const float* __restrict__ X,
                const float* __restrict__ rc,
                const float* __restrict__ rs,
                const float* __restrict__ re,
                const int*   __restrict__ Nbrs,
                const int*   __restrict__ NbrsZ,
                float*       __restrict__ out)
{
    __shared__ float2 sRT[APB][MM];
    __shared__ int    sCnt[APB];
    __shared__ float2 sPart[TH1];

    const int tid  = threadIdx.x;
    const int warp = tid >> 5;
    const int lane = tid & 31;
    const int baseAtom = blockIdx.x * APB;      // atom = b*N + n

    // ---------------- Phase A ----------------
    if (warp < APB) {
        const int atom = baseAtom + warp;
        const int b    = atom >> 11;
        const float* xp = X + atom * 3;
        const float x0 = xp[0], x1 = xp[1], x2 = xp[2];

        const int nb = Nbrs [atom * MM + lane];
        const int z  = NbrsZ[atom * MM + lane];
        const float* np_ = X + ((b << 11) + nb) * 3;
        const float dx = np_[0] - x0;
        const float dy = np_[1] - x1;
        const float dz = np_[2] - x2;
        const float R  = sqrt_fast(dx*dx + dy*dy + dz*dz);

        int t = -1;
        if      (z == 1)  t = 0;
        else if (z == 6)  t = 1;
        else if (z == 7)  t = 2;
        else if (z == 8)  t = 3;
        else if (z == 16) t = 4;

        const unsigned mask = __ballot_sync(0xffffffffu, t >= 0);
        if (t >= 0) {
            const int pos = __popc(mask & ((1u << lane) - 1u));
            sRT[warp][pos] = make_float2(R, __int_as_float(t));
        }
        if (lane == 0) sCnt[warp] = __popc(mask);
    }
    __syncthreads();

    // ---------------- Phase B ----------------
    const int g = tid / PP;        // atom within block
    const int j = tid % PP;        // radial index p
    const int atom = baseAtom + g;

    const float myrc  = __ldg(rc + j);
    const float myrs  = __ldg(rs + j);
    const float nre2  = -__ldg(re + j) * 1.44269504088896f;  // fold log2(e)
    const float pi_rc = 3.14159265358979f / myrc;
    const float2* rt  = sRT[g];
    const int total   = sCnt[g];

    float acc[TT];
    #pragma unroll
    for (int tt = 0; tt < TT; tt++) acc[tt] = 0.0f;

    int m = 0;
    for (; m + 2 <= total; m += 2) {
        const float2 a0 = rt[m];
        const float2 a1 = rt[m + 1];
        const float R0 = a0.x, R1 = a1.x;
        const int   t0 = __float_as_int(a0.y);
        const int   t1 = __float_as_int(a1.y);
        const float d0 = R0 - myrs;
        const float d1 = R1 - myrs;
        const float e0 = ex2_fast(nre2 * d0 * d0);
        const float e1 = ex2_fast(nre2 * d1 * d1);
        const float c0 = __cosf(R0 * pi_rc);
        const float c1 = __cosf(R1 * pi_rc);
        float f0 = fmaf(c0, 0.5f, 0.5f);
        float f1 = fmaf(c1, 0.5f, 0.5f);
        f0 = (R0 <= myrc) ? f0 : 0.0f;
        f1 = (R1 <= myrc) ? f1 : 0.0f;
        const float v0 = e0 * f0;
        const float v1 = e1 * f1;
        #pragma unroll
        for (int tt = 0; tt < TT; tt++) {
            if (t0 == tt) acc[tt] += v0;
            if (t1 == tt) acc[tt] += v1;
        }
    }
    if (m < total) {
        const float2 a0 = rt[m];
        const float R0 = a0.x;
        const int   t0 = __float_as_int(a0.y);
        const float d0 = R0 - myrs;
        const float e0 = ex2_fast(nre2 * d0 * d0);
        const float c0 = __cosf(R0 * pi_rc);
        float f0 = fmaf(c0, 0.5f, 0.5f);
        f0 = (R0 <= myrc) ? f0 : 0.0f;
        const float v0 = e0 * f0;
        #pragma unroll
        for (int tt = 0; tt < TT; tt++) {
            if (t0 == tt) acc[tt] += v0;
        }
    }

    float s = 0.0f, s2 = 0.0f;
    {
        float* op = out + (size_t)atom * CC;
        #pragma unroll
        for (int tt = 0; tt < TT; tt++) {
            const float a = acc[tt];
            op[tt * PP + j] = a;
            s  += a;
            s2 = fmaf(a, a, s2);
        }
    }
    sPart[tid] = make_float2(s, s2);
    __syncthreads();

    // ---------------- Phase C: per-atom reduce of (s,s2) ----------------
    if (warp < APB) {
        const float2 p0 = sPart[warp * PP + lane];
        float s  = p0.x;
        float s2 = p0.y;
        if (lane < PP - 32) {
            const float2 p1 = sPart[warp * PP + 32 + lane];
            s  += p1.x;
            s2 += p1.y;
        }
        #pragma unroll
        for (int o = 16; o > 0; o >>= 1) {
            s  += __shfl_down_sync(0xffffffffu, s,  o);
            s2 += __shfl_down_sync(0xffffffffu, s2, o);
        }
        if (lane == 0) g_part[baseAtom + warp] = make_float2(s, s2);
    }
}

// ---------------------------------------------------------------------------
// Kernel 2: BatchNorm normalize. One block per n (2048 blocks, 256 threads).
// Warp 0 reduces the 16 per-atom partials -> mean/inv. Then thread tid<240
// handles float4 column c4 = tid%60 for 4 rows b = (tid/60)*4 + r:
// 4 vectorized loads batched, then 4 stores.
// ---------------------------------------------------------------------------
__global__ __launch_bounds__(256)
void norm_kernel(float4* __restrict__ out4)
{
    const int n   = blockIdx.x;
    const int tid = threadIdx.x;

    __shared__ float sMean, sInv;

    if (tid < 32) {
        float s = 0.0f, s2 = 0.0f;
        if (tid < BB) {
            const float2 p = g_part[tid * NN + n];
            s = p.x; s2 = p.y;
        }
        #pragma unroll
        for (int o = 8; o > 0; o >>= 1) {
            s  += __shfl_down_sync(0xffffffffu, s,  o);
            s2 += __shfl_down_sync(0xffffffffu, s2, o);
        }
        if (tid == 0) {
            const float invn = 1.0f / (float)(BB * CC);
            const float mean = s * invn;
            float var = s2 * invn - mean * mean;
            var = fmaxf(var, 0.0f);
            sMean = mean;
            sInv  = rsqrtf(var + 1e-5f);
        }
    }
    __syncthreads();

    if (tid < 240) {
        const float mean = sMean;
        const float inv  = sInv;
        const int bq = tid / 60;              // 0..3
        const int c4 = tid % 60;              // float4 index within row

        float4 v[4];
        size_t idx[4];
        #pragma unroll
        for (int r = 0; r < 4; r++) {
            const int b = bq * 4 + r;
            idx[r] = (size_t)(b * NN + n) * (CC / 4) + c4;
            v[r] = out4[idx[r]];
        }
        #pragma unroll
        for (int r = 0; r < 4; r++) {
            v[r].x = (v[r].x - mean) * inv;
            v[r].y = (v[r].y - mean) * inv;
            v[r].z = (v[r].z - mean) * inv;
            v[r].w = (v[r].w - mean) * inv;
            out4[idx[r]] = v[r];
        }
    }
}

// ---------------------------------------------------------------------------
extern "C" void kernel_launch(void* const* d_in, const int* in_sizes, int n_in,
                              void* d_out, int out_size)
{
    const float* X     = (const float*)d_in[0];
    const float* rc    = (const float*)d_in[1];
    const float* rs    = (const float*)d_in[2];
    const float* re    = (const float*)d_in[3];
    const int*   Nbrs  = (const int*)  d_in[4];
    const int*   NbrsZ = (const int*)  d_in[5];

    const int nAtoms = BB * NN;                 // 32768
    rsf_kernel<<<nAtoms / APB, TH1>>>(X, rc, rs, re, Nbrs, NbrsZ, (float*)d_out);
    norm_kernel<<<NN, 256>>>((float4*)d_out);
}